// round 1
// baseline (speedup 1.0000x reference)
#include <cuda_runtime.h>

// Problem constants
constexpr int B_ = 128;
constexpr int T_ = 1024;
constexpr int D_ = 512;
constexpr int H_ = 1024;
constexpr int G_ = 3 * H_;       // 3072 gate columns

// Persistent-kernel config
constexpr int NT  = 48;          // n-tiles of 64 gate-cols
constexpr int KS  = 3;           // k-splits
constexpr int NB  = NT * KS;     // 144 CTAs (<= 148 SMs, single co-resident wave)
constexpr int KCH = 344;         // k-chunk (multiple of 8; last chunk = 336)

// Scratch (device globals — allocation-free kernel_launch)
__device__ float g_IG[(size_t)T_ * B_ * G_];   // precomputed x@w_ih^T + b  (1.61 GB)
__device__ float g_h[2][B_ * H_];              // ping-pong hidden state
__device__ float g_part[KS][B_ * G_];          // k-split partials (deterministic reduce)
__device__ unsigned int g_cnt;                 // grid barrier counter

// ---------------------------------------------------------------------------
// init: zero h0, reset barrier counter (must be per-launch deterministic)
// ---------------------------------------------------------------------------
__global__ void init_kernel() {
    unsigned idx = blockIdx.x * blockDim.x + threadIdx.x;
    if (idx == 0) g_cnt = 0u;
    for (unsigned i = idx; i < (unsigned)(B_ * H_); i += gridDim.x * blockDim.x)
        g_h[0][i] = 0.0f;
}

// ---------------------------------------------------------------------------
// IG GEMM: g_IG[t][b][g] = sum_k x[b][t][k] * w_ih[g][k] + bias[g]
// Classic 128x128x8 fp32 tile, 256 threads, 8x8 microtile (split 4+4 for
// conflict-free LDS.128).  blockIdx.y == t (since BM == B == 128).
// ---------------------------------------------------------------------------
__global__ __launch_bounds__(256) void ig_gemm(const float* __restrict__ x,
                                               const float* __restrict__ w_ih,
                                               const float* __restrict__ bias) {
    __shared__ float As[8][128];   // As[k][b]
    __shared__ float Bs[8][128];   // Bs[k][n]

    const int t   = blockIdx.y;
    const int n0  = blockIdx.x * 128;
    const int tid = threadIdx.x;

    const int lm = tid >> 1;            // 0..127 row for loads
    const int lk = (tid & 1) * 4;       // 0 or 4
    const int tx = tid & 15;
    const int ty = tid >> 4;

    float acc[8][8];
#pragma unroll
    for (int i = 0; i < 8; i++)
#pragma unroll
        for (int j = 0; j < 8; j++) acc[i][j] = 0.0f;

    const float* xrow = x + ((size_t)lm * T_ + t) * D_ + lk;          // batch row lm
    const float* wrow = w_ih + (size_t)(n0 + lm) * D_ + lk;           // gate row n0+lm

    for (int k0 = 0; k0 < D_; k0 += 8) {
        float4 av = *reinterpret_cast<const float4*>(xrow + k0);
        float4 bv = *reinterpret_cast<const float4*>(wrow + k0);
        As[lk + 0][lm] = av.x; As[lk + 1][lm] = av.y;
        As[lk + 2][lm] = av.z; As[lk + 3][lm] = av.w;
        Bs[lk + 0][lm] = bv.x; Bs[lk + 1][lm] = bv.y;
        Bs[lk + 2][lm] = bv.z; Bs[lk + 3][lm] = bv.w;
        __syncthreads();
#pragma unroll
        for (int k = 0; k < 8; k++) {
            float a[8], b8[8];
            *reinterpret_cast<float4*>(&a[0])  = *reinterpret_cast<const float4*>(&As[k][ty * 4]);
            *reinterpret_cast<float4*>(&a[4])  = *reinterpret_cast<const float4*>(&As[k][64 + ty * 4]);
            *reinterpret_cast<float4*>(&b8[0]) = *reinterpret_cast<const float4*>(&Bs[k][tx * 4]);
            *reinterpret_cast<float4*>(&b8[4]) = *reinterpret_cast<const float4*>(&Bs[k][64 + tx * 4]);
#pragma unroll
            for (int i = 0; i < 8; i++)
#pragma unroll
                for (int j = 0; j < 8; j++)
                    acc[i][j] += a[i] * b8[j];
        }
        __syncthreads();
    }

#pragma unroll
    for (int i = 0; i < 8; i++) {
        int r = (i < 4) ? (ty * 4 + i) : (64 + ty * 4 + (i - 4));
        float* orow = g_IG + ((size_t)t * B_ + r) * G_ + n0;
#pragma unroll
        for (int jj = 0; jj < 2; jj++) {
            int c = jj ? (64 + tx * 4) : (tx * 4);
            float4 v;
            v.x = acc[i][jj * 4 + 0] + __ldg(&bias[n0 + c + 0]);
            v.y = acc[i][jj * 4 + 1] + __ldg(&bias[n0 + c + 1]);
            v.z = acc[i][jj * 4 + 2] + __ldg(&bias[n0 + c + 2]);
            v.w = acc[i][jj * 4 + 3] + __ldg(&bias[n0 + c + 3]);
            *reinterpret_cast<float4*>(orow + c) = v;
        }
    }
}

// ---------------------------------------------------------------------------
// software grid barrier (all NB CTAs co-resident; monotonic counter)
// ---------------------------------------------------------------------------
__device__ __forceinline__ void grid_sync(unsigned int target) {
    __threadfence();
    __syncthreads();
    if (threadIdx.x == 0) {
        atomicAdd(&g_cnt, 1u);
        while (*reinterpret_cast<volatile unsigned int*>(&g_cnt) < target) { }
    }
    __syncthreads();
}

// ---------------------------------------------------------------------------
// Persistent GRU recurrence.
// Per step: 144 CTAs compute hg = h @ w_hh^T as [128 x 64]-tile x 3 k-split
// partials -> barrier -> fused gating updates h (ping-pong) -> barrier.
// Cross-CTA data (h, partials) via __ldcg (L2), w_hh slice stays L1-hot.
// ---------------------------------------------------------------------------
__global__ __launch_bounds__(256, 1) void gru_persist(const float* __restrict__ w_hh,
                                                      const float* __restrict__ bn) {
    __shared__ float Hs[8][128];   // Hs[k][b]
    __shared__ float Ws[8][64];    // Ws[k][n]

    const int tid  = threadIdx.x;
    const int nt   = blockIdx.x % NT;
    const int ks   = blockIdx.x / NT;
    const int n0   = nt * 64;
    const int kbeg = ks * KCH;
    const int kend = min(H_, kbeg + KCH);

    const int tx = tid & 15, ty = tid >> 4;
    const int col0 = tx * 4, row0 = ty * 8;
    const int lm = tid >> 1, lk = (tid & 1) * 4;      // Hs loader
    const int wn = tid & 63, wk = (tid >> 6) * 2;     // Ws loader

    const float* wrow = w_hh + (size_t)(n0 + wn) * H_;

    unsigned round = 0;
    int cur = 0;

    for (int t = 0; t < T_; t++) {
        float acc[8][4];
#pragma unroll
        for (int i = 0; i < 8; i++)
#pragma unroll
            for (int j = 0; j < 4; j++) acc[i][j] = 0.0f;

        const float* hsrc = g_h[cur];

        for (int k0 = kbeg; k0 < kend; k0 += 8) {
            float4 hv = __ldcg(reinterpret_cast<const float4*>(hsrc + lm * H_ + k0 + lk));
            float2 wv = *reinterpret_cast<const float2*>(wrow + k0 + wk);
            Hs[lk + 0][lm] = hv.x; Hs[lk + 1][lm] = hv.y;
            Hs[lk + 2][lm] = hv.z; Hs[lk + 3][lm] = hv.w;
            Ws[wk + 0][wn] = wv.x; Ws[wk + 1][wn] = wv.y;
            __syncthreads();
#pragma unroll
            for (int k = 0; k < 8; k++) {
                float a[8], c4[4];
                *reinterpret_cast<float4*>(&a[0]) = *reinterpret_cast<const float4*>(&Hs[k][row0]);
                *reinterpret_cast<float4*>(&a[4]) = *reinterpret_cast<const float4*>(&Hs[k][row0 + 4]);
                *reinterpret_cast<float4*>(&c4[0]) = *reinterpret_cast<const float4*>(&Ws[k][col0]);
#pragma unroll
                for (int i = 0; i < 8; i++)
#pragma unroll
                    for (int j = 0; j < 4; j++)
                        acc[i][j] += a[i] * c4[j];
            }
            __syncthreads();
        }

        // partial writes (deterministic k-split buffers)
#pragma unroll
        for (int i = 0; i < 8; i++) {
            float4 v = make_float4(acc[i][0], acc[i][1], acc[i][2], acc[i][3]);
            *reinterpret_cast<float4*>(&g_part[ks][(row0 + i) * G_ + n0 + col0]) = v;
        }

        round++; grid_sync(round * NB);

        // fused gating: h_new = n + z*(h - n)
        const float* ig_t = g_IG + (size_t)t * B_ * G_;
        float* hdst = g_h[cur ^ 1];
        for (int i = blockIdx.x * 256 + tid; i < B_ * H_; i += NB * 256) {
            int b = i >> 10;            // / H_
            int j = i & (H_ - 1);
            int base = b * G_;
            float hgr = 0.f, hgz = 0.f, hgn = 0.f;
#pragma unroll
            for (int s = 0; s < KS; s++) {
                hgr += __ldcg(&g_part[s][base + j]);
                hgz += __ldcg(&g_part[s][base + H_ + j]);
                hgn += __ldcg(&g_part[s][base + 2 * H_ + j]);
            }
            float igr = ig_t[base + j];
            float igz = ig_t[base + H_ + j];
            float ign = ig_t[base + 2 * H_ + j];
            float hold = __ldcg(&hsrc[i]);
            float r = 1.0f / (1.0f + expf(-(igr + hgr)));
            float z = 1.0f / (1.0f + expf(-(igz + hgz)));
            float nn = tanhf(ign + r * (hgn + bn[j]));
            hdst[i] = nn + z * (hold - nn);
        }

        round++; grid_sync(round * NB);
        cur ^= 1;
    }
    // after 1024 steps (even), final h is in g_h[0]
}

// ---------------------------------------------------------------------------
// final projection: out[b] = h_final[b,:] . w_out + b_out
// ---------------------------------------------------------------------------
__global__ void out_kernel(const float* __restrict__ w_out,
                           const float* __restrict__ b_out,
                           float* __restrict__ out) {
    __shared__ float red[256];
    int b = blockIdx.x;
    float s = 0.0f;
    for (int j = threadIdx.x; j < H_; j += blockDim.x)
        s += g_h[0][b * H_ + j] * w_out[j];
    red[threadIdx.x] = s;
    __syncthreads();
    for (int off = 128; off > 0; off >>= 1) {
        if (threadIdx.x < off) red[threadIdx.x] += red[threadIdx.x + off];
        __syncthreads();
    }
    if (threadIdx.x == 0) out[b] = red[0] + b_out[0];
}

// ---------------------------------------------------------------------------
extern "C" void kernel_launch(void* const* d_in, const int* in_sizes, int n_in,
                              void* d_out, int out_size) {
    const float* x     = (const float*)d_in[0];
    const float* w_ih  = (const float*)d_in[1];
    const float* w_hh  = (const float*)d_in[2];
    const float* b     = (const float*)d_in[3];
    const float* bn    = (const float*)d_in[4];
    const float* w_out = (const float*)d_in[5];
    const float* b_out = (const float*)d_in[6];
    float* out = (float*)d_out;

    init_kernel<<<128, 256>>>();

    dim3 g1(G_ / 128, T_);
    ig_gemm<<<g1, 256>>>(x, w_ih, b);

    gru_persist<<<NB, 256>>>(w_hh, bn);

    out_kernel<<<B_, 256>>>(w_out, b_out, out);
}

// round 2
// speedup vs baseline: 1.6032x; 1.6032x over previous
#include <cuda_runtime.h>
#include <cstdint>

// Problem constants
constexpr int B_ = 128;
constexpr int T_ = 1024;
constexpr int D_ = 512;
constexpr int H_ = 1024;
constexpr int G_ = 3 * H_;       // 3072 gate columns

// Recurrent persistent-kernel config
constexpr int NT  = 64;          // n-tiles (16 h-cols -> 48 gate cols each)
constexpr int KS  = 2;           // k-splits
constexpr int NB  = NT * KS;     // 128 CTAs (co-resident on 148 SMs)
constexpr int KREC = H_ / KS;    // 512 k per CTA

// Shared GEMM tile config (both kernels): CTA 128x48, K-chunk 64
constexpr int KC = 64;
constexpr int SA = KC + 4;       // stride 68 floats: (4*row + k) % 32 -> conflict-free frags
constexpr int SMEM_BYTES = (2 * 128 * SA + 2 * 48 * SA) * 4;   // 95744 B

// Device scratch
__device__ float g_IG[(size_t)T_ * B_ * G_];      // x@w_ih^T + b
__device__ float g_h_hi[2][B_ * H_];              // hidden state tf32-hi (ping-pong)
__device__ float g_h_lo[2][B_ * H_];              // hidden state residual
__device__ float g_whh_hi[(size_t)G_ * H_];       // w_hh tf32 split
__device__ float g_whh_lo[(size_t)G_ * H_];
__device__ float g_part[KS][B_ * G_];             // k-split partials
__device__ unsigned int g_cnt;

// ---------------------------------------------------------------------------
// helpers
// ---------------------------------------------------------------------------
__device__ __forceinline__ float tf32_rn(float f) {
    uint32_t u;
    asm("cvt.rna.tf32.f32 %0, %1;" : "=r"(u) : "f"(f));
    return __uint_as_float(u);
}
__device__ __forceinline__ void split2(float f, float& hi, float& lo) {
    hi = tf32_rn(f);
    lo = f - hi;
}
__device__ __forceinline__ void mma_tf32(float* d, const uint32_t* a, const uint32_t* b) {
    asm("mma.sync.aligned.m16n8k8.row.col.f32.tf32.tf32.f32 "
        "{%0,%1,%2,%3},{%4,%5,%6,%7},{%8,%9},{%0,%1,%2,%3};"
        : "+f"(d[0]), "+f"(d[1]), "+f"(d[2]), "+f"(d[3])
        : "r"(a[0]), "r"(a[1]), "r"(a[2]), "r"(a[3]), "r"(b[0]), "r"(b[1]));
}

// ---------------------------------------------------------------------------
// init: zero h0 (hi/lo), reset barrier counter
// ---------------------------------------------------------------------------
__global__ void init_kernel() {
    unsigned idx = blockIdx.x * blockDim.x + threadIdx.x;
    if (idx == 0) g_cnt = 0u;
    for (unsigned i = idx; i < (unsigned)(B_ * H_); i += gridDim.x * blockDim.x) {
        g_h_hi[0][i] = 0.0f;
        g_h_lo[0][i] = 0.0f;
    }
}

// one-time tf32 split of w_hh
__global__ void split_whh(const float* __restrict__ w) {
    size_t i = (size_t)blockIdx.x * blockDim.x + threadIdx.x;
    if (i < (size_t)G_ * H_) {
        float hi, lo;
        split2(w[i], hi, lo);
        g_whh_hi[i] = hi;
        g_whh_lo[i] = lo;
    }
}

// ---------------------------------------------------------------------------
// IG GEMM (3xTF32 mma): g_IG[t][b][g] = x[b][t][:] . w_ih[g][:] + bias[g]
// grid = (G/48, T); CTA tile 128x48xK512, warps 4Mx2N (32x24 each)
// ---------------------------------------------------------------------------
__global__ __launch_bounds__(256) void ig_gemm(const float* __restrict__ x,
                                               const float* __restrict__ w_ih,
                                               const float* __restrict__ bias) {
    extern __shared__ float sm[];
    float* Xh = sm;                  // [128][SA]
    float* Xl = Xh + 128 * SA;
    float* Wh = Xl + 128 * SA;       // [48][SA]
    float* Wl = Wh + 48 * SA;

    const int t  = blockIdx.y;
    const int n0 = blockIdx.x * 48;
    const int tid = threadIdx.x;
    const int warp = tid >> 5, lane = tid & 31;
    const int g = lane >> 2, c = lane & 3;
    const int wm = warp >> 1, wn = warp & 1;
    const int rb = wm * 32, cb = wn * 24;

    const int srow = tid >> 4;       // 0..15
    const int sc4  = (tid & 15) * 4; // 0..60

    float acc[2][3][4];
#pragma unroll
    for (int m = 0; m < 2; m++)
#pragma unroll
        for (int n = 0; n < 3; n++)
#pragma unroll
            for (int q = 0; q < 4; q++) acc[m][n][q] = 0.0f;

    for (int k0 = 0; k0 < D_; k0 += KC) {
        // stage X (split on the fly)
#pragma unroll
        for (int r = 0; r < 8; r++) {
            int row = srow + r * 16;
            float4 v = *reinterpret_cast<const float4*>(x + ((size_t)row * T_ + t) * D_ + k0 + sc4);
            float h0, l0, h1, l1, h2, l2, h3, l3;
            split2(v.x, h0, l0); split2(v.y, h1, l1);
            split2(v.z, h2, l2); split2(v.w, h3, l3);
            float* ph = &Xh[row * SA + sc4];
            float* pl = &Xl[row * SA + sc4];
            ph[0] = h0; ph[1] = h1; ph[2] = h2; ph[3] = h3;
            pl[0] = l0; pl[1] = l1; pl[2] = l2; pl[3] = l3;
        }
        // stage W
#pragma unroll
        for (int r = 0; r < 3; r++) {
            int n = srow + r * 16;
            float4 v = *reinterpret_cast<const float4*>(w_ih + (size_t)(n0 + n) * D_ + k0 + sc4);
            float h0, l0, h1, l1, h2, l2, h3, l3;
            split2(v.x, h0, l0); split2(v.y, h1, l1);
            split2(v.z, h2, l2); split2(v.w, h3, l3);
            float* ph = &Wh[n * SA + sc4];
            float* pl = &Wl[n * SA + sc4];
            ph[0] = h0; ph[1] = h1; ph[2] = h2; ph[3] = h3;
            pl[0] = l0; pl[1] = l1; pl[2] = l2; pl[3] = l3;
        }
        __syncthreads();

#pragma unroll
        for (int kk = 0; kk < KC; kk += 8) {
            uint32_t ah[2][4], al[2][4];
#pragma unroll
            for (int m = 0; m < 2; m++) {
                int r0 = rb + m * 16 + g;
                ah[m][0] = __float_as_uint(Xh[r0 * SA + kk + c]);
                ah[m][1] = __float_as_uint(Xh[(r0 + 8) * SA + kk + c]);
                ah[m][2] = __float_as_uint(Xh[r0 * SA + kk + c + 4]);
                ah[m][3] = __float_as_uint(Xh[(r0 + 8) * SA + kk + c + 4]);
                al[m][0] = __float_as_uint(Xl[r0 * SA + kk + c]);
                al[m][1] = __float_as_uint(Xl[(r0 + 8) * SA + kk + c]);
                al[m][2] = __float_as_uint(Xl[r0 * SA + kk + c + 4]);
                al[m][3] = __float_as_uint(Xl[(r0 + 8) * SA + kk + c + 4]);
            }
#pragma unroll
            for (int n = 0; n < 3; n++) {
                int nr = cb + n * 8 + g;
                uint32_t bh[2], bl[2];
                bh[0] = __float_as_uint(Wh[nr * SA + kk + c]);
                bh[1] = __float_as_uint(Wh[nr * SA + kk + c + 4]);
                bl[0] = __float_as_uint(Wl[nr * SA + kk + c]);
                bl[1] = __float_as_uint(Wl[nr * SA + kk + c + 4]);
#pragma unroll
                for (int m = 0; m < 2; m++) {
                    mma_tf32(acc[m][n], ah[m], bh);
                    mma_tf32(acc[m][n], ah[m], bl);
                    mma_tf32(acc[m][n], al[m], bh);
                }
            }
        }
        __syncthreads();
    }

    // epilogue: add bias, store
#pragma unroll
    for (int m = 0; m < 2; m++) {
#pragma unroll
        for (int n = 0; n < 3; n++) {
            int row = rb + m * 16 + g;
            int lc  = cb + n * 8 + 2 * c;
            int gc  = n0 + lc;
            float b0 = __ldg(&bias[gc]), b1 = __ldg(&bias[gc + 1]);
            float2 v0 = make_float2(acc[m][n][0] + b0, acc[m][n][1] + b1);
            float2 v1 = make_float2(acc[m][n][2] + b0, acc[m][n][3] + b1);
            *reinterpret_cast<float2*>(&g_IG[((size_t)t * B_ + row) * G_ + gc]) = v0;
            *reinterpret_cast<float2*>(&g_IG[((size_t)t * B_ + row + 8) * G_ + gc]) = v1;
        }
    }
}

// ---------------------------------------------------------------------------
// grid barrier
// ---------------------------------------------------------------------------
__device__ __forceinline__ void grid_sync(unsigned int target) {
    __threadfence();
    __syncthreads();
    if (threadIdx.x == 0) {
        atomicAdd(&g_cnt, 1u);
        while (*reinterpret_cast<volatile unsigned int*>(&g_cnt) < target) { }
    }
    __syncthreads();
}

// ---------------------------------------------------------------------------
// Persistent GRU recurrence (3xTF32 mma).
// CTA = (nt, ks): gate cols {g*H + nt*16 .. +16} for g=0..2 (N=48), K slice 512.
// ---------------------------------------------------------------------------
__global__ __launch_bounds__(256, 1) void gru_persist(const float* __restrict__ bn) {
    extern __shared__ float sm[];
    float* Ah = sm;                  // h tile [128][SA]
    float* Al = Ah + 128 * SA;
    float* Wh = Al + 128 * SA;       // w slab [48][SA]
    float* Wl = Wh + 48 * SA;

    const int tid = threadIdx.x;
    const int nt = blockIdx.x % NT;
    const int ks = blockIdx.x / NT;
    const int j0 = nt * 16;
    const int kbeg = ks * KREC;

    const int warp = tid >> 5, lane = tid & 31;
    const int g = lane >> 2, c = lane & 3;
    const int wm = warp >> 1, wn = warp & 1;
    const int rb = wm * 32, cb = wn * 24;
    const int srow = tid >> 4;
    const int sc4  = (tid & 15) * 4;

    unsigned round = 0;
    int cur = 0;

    for (int t = 0; t < T_; t++) {
        float acc[2][3][4];
#pragma unroll
        for (int m = 0; m < 2; m++)
#pragma unroll
            for (int n = 0; n < 3; n++)
#pragma unroll
                for (int q = 0; q < 4; q++) acc[m][n][q] = 0.0f;

        const float* hhi = g_h_hi[cur];
        const float* hlo = g_h_lo[cur];

        for (int k0 = kbeg; k0 < kbeg + KREC; k0 += KC) {
            // stage h tile (L2 reads — cross-CTA data)
#pragma unroll
            for (int r = 0; r < 8; r++) {
                int row = srow + r * 16;
                float4 vh = __ldcg(reinterpret_cast<const float4*>(hhi + row * H_ + k0 + sc4));
                float4 vl = __ldcg(reinterpret_cast<const float4*>(hlo + row * H_ + k0 + sc4));
                float* ph = &Ah[row * SA + sc4];
                float* pl = &Al[row * SA + sc4];
                ph[0] = vh.x; ph[1] = vh.y; ph[2] = vh.z; ph[3] = vh.w;
                pl[0] = vl.x; pl[1] = vl.y; pl[2] = vl.z; pl[3] = vl.w;
            }
            // stage w slab (pre-split, L2/L1 resident)
#pragma unroll
            for (int r = 0; r < 3; r++) {
                int n = srow + r * 16;
                int grow = (n >> 4) * H_ + j0 + (n & 15);
                float4 vh = *reinterpret_cast<const float4*>(g_whh_hi + (size_t)grow * H_ + k0 + sc4);
                float4 vl = *reinterpret_cast<const float4*>(g_whh_lo + (size_t)grow * H_ + k0 + sc4);
                float* ph = &Wh[n * SA + sc4];
                float* pl = &Wl[n * SA + sc4];
                ph[0] = vh.x; ph[1] = vh.y; ph[2] = vh.z; ph[3] = vh.w;
                pl[0] = vl.x; pl[1] = vl.y; pl[2] = vl.z; pl[3] = vl.w;
            }
            __syncthreads();

#pragma unroll
            for (int kk = 0; kk < KC; kk += 8) {
                uint32_t ah[2][4], al[2][4];
#pragma unroll
                for (int m = 0; m < 2; m++) {
                    int r0 = rb + m * 16 + g;
                    ah[m][0] = __float_as_uint(Ah[r0 * SA + kk + c]);
                    ah[m][1] = __float_as_uint(Ah[(r0 + 8) * SA + kk + c]);
                    ah[m][2] = __float_as_uint(Ah[r0 * SA + kk + c + 4]);
                    ah[m][3] = __float_as_uint(Ah[(r0 + 8) * SA + kk + c + 4]);
                    al[m][0] = __float_as_uint(Al[r0 * SA + kk + c]);
                    al[m][1] = __float_as_uint(Al[(r0 + 8) * SA + kk + c]);
                    al[m][2] = __float_as_uint(Al[r0 * SA + kk + c + 4]);
                    al[m][3] = __float_as_uint(Al[(r0 + 8) * SA + kk + c + 4]);
                }
#pragma unroll
                for (int n = 0; n < 3; n++) {
                    int nr = cb + n * 8 + g;
                    uint32_t bh[2], bl[2];
                    bh[0] = __float_as_uint(Wh[nr * SA + kk + c]);
                    bh[1] = __float_as_uint(Wh[nr * SA + kk + c + 4]);
                    bl[0] = __float_as_uint(Wl[nr * SA + kk + c]);
                    bl[1] = __float_as_uint(Wl[nr * SA + kk + c + 4]);
#pragma unroll
                    for (int m = 0; m < 2; m++) {
                        mma_tf32(acc[m][n], ah[m], bh);
                        mma_tf32(acc[m][n], ah[m], bl);
                        mma_tf32(acc[m][n], al[m], bh);
                    }
                }
            }
            __syncthreads();
        }

        // write k-split partials
#pragma unroll
        for (int m = 0; m < 2; m++) {
#pragma unroll
            for (int n = 0; n < 3; n++) {
                int row = rb + m * 16 + g;
                int lc  = cb + n * 8 + 2 * c;
                int gcol = (lc >> 4) * H_ + j0 + (lc & 15);
                *reinterpret_cast<float2*>(&g_part[ks][row * G_ + gcol]) =
                    make_float2(acc[m][n][0], acc[m][n][1]);
                *reinterpret_cast<float2*>(&g_part[ks][(row + 8) * G_ + gcol]) =
                    make_float2(acc[m][n][2], acc[m][n][3]);
            }
        }

        round++; grid_sync(round * NB);

        // fused gating: h_new = n + z*(h - n); store tf32 split
        const float* ig_t = g_IG + (size_t)t * B_ * G_;
        float* dhi = g_h_hi[cur ^ 1];
        float* dlo = g_h_lo[cur ^ 1];
        for (int i = blockIdx.x * 256 + tid; i < B_ * H_; i += NB * 256) {
            int b = i >> 10;
            int j = i & (H_ - 1);
            int base = b * G_;
            float hgr = __ldcg(&g_part[0][base + j])          + __ldcg(&g_part[1][base + j]);
            float hgz = __ldcg(&g_part[0][base + H_ + j])     + __ldcg(&g_part[1][base + H_ + j]);
            float hgn = __ldcg(&g_part[0][base + 2 * H_ + j]) + __ldcg(&g_part[1][base + 2 * H_ + j]);
            float igr = ig_t[base + j];
            float igz = ig_t[base + H_ + j];
            float ign = ig_t[base + 2 * H_ + j];
            float hold = __ldcg(&hhi[i]) + __ldcg(&hlo[i]);
            float r = 1.0f / (1.0f + expf(-(igr + hgr)));
            float z = 1.0f / (1.0f + expf(-(igz + hgz)));
            float nn = tanhf(ign + r * (hgn + bn[j]));
            float hnew = nn + z * (hold - nn);
            float hi, lo;
            split2(hnew, hi, lo);
            dhi[i] = hi;
            dlo[i] = lo;
        }

        round++; grid_sync(round * NB);
        cur ^= 1;
    }
}

// ---------------------------------------------------------------------------
// final projection
// ---------------------------------------------------------------------------
__global__ void out_kernel(const float* __restrict__ w_out,
                           const float* __restrict__ b_out,
                           float* __restrict__ out) {
    __shared__ float red[256];
    int b = blockIdx.x;
    float s = 0.0f;
    for (int j = threadIdx.x; j < H_; j += blockDim.x)
        s += (g_h_hi[0][b * H_ + j] + g_h_lo[0][b * H_ + j]) * w_out[j];
    red[threadIdx.x] = s;
    __syncthreads();
    for (int off = 128; off > 0; off >>= 1) {
        if (threadIdx.x < off) red[threadIdx.x] += red[threadIdx.x + off];
        __syncthreads();
    }
    if (threadIdx.x == 0) out[b] = red[0] + b_out[0];
}

// ---------------------------------------------------------------------------
extern "C" void kernel_launch(void* const* d_in, const int* in_sizes, int n_in,
                              void* d_out, int out_size) {
    const float* x     = (const float*)d_in[0];
    const float* w_ih  = (const float*)d_in[1];
    const float* w_hh  = (const float*)d_in[2];
    const float* b     = (const float*)d_in[3];
    const float* bn    = (const float*)d_in[4];
    const float* w_out = (const float*)d_in[5];
    const float* b_out = (const float*)d_in[6];
    float* out = (float*)d_out;

    cudaFuncSetAttribute(ig_gemm, cudaFuncAttributeMaxDynamicSharedMemorySize, SMEM_BYTES);
    cudaFuncSetAttribute(gru_persist, cudaFuncAttributeMaxDynamicSharedMemorySize, SMEM_BYTES);

    init_kernel<<<128, 256>>>();
    split_whh<<<(G_ * H_) / 256, 256>>>(w_hh);

    dim3 gig(G_ / 48, T_);
    ig_gemm<<<gig, 256, SMEM_BYTES>>>(x, w_ih, b);

    gru_persist<<<NB, 256, SMEM_BYTES>>>(bn);

    out_kernel<<<B_, 256>>>(w_out, b_out, out);
}

// round 4
// speedup vs baseline: 2.6457x; 1.6502x over previous
#include <cuda_runtime.h>
#include <cuda_fp16.h>
#include <cstdint>

// Problem constants
constexpr int B_ = 128;
constexpr int T_ = 1024;
constexpr int D_ = 512;
constexpr int H_ = 1024;
constexpr int G_ = 3 * H_;            // 3072

// Recurrence: 128 CTAs = NT n-tiles x KS k-splits
constexpr int NT = 32;                // 96 gate cols per CTA
constexpr int KS = 4;                 // k slice 256
constexpr int NB = NT * KS;           // 128
constexpr int NCTA = G_ / NT;         // 96
constexpr int KCTA = H_ / KS;         // 256

// IG GEMM config
constexpr int IGN  = 64;              // gate cols per CTA
constexpr int IGNT = G_ / IGN;        // 48
constexpr int TG   = 4;               // t values per CTA

// Shared memory layouts (chunk = 16B = 8 half). Swizzle: chunk' = chunk ^ (row&7).
constexpr int R_WH = 0;                        // 96 rows x 32 chunks
constexpr int R_WL = 96 * 32 * 16;             // 49152
constexpr int R_AH = 2 * 96 * 32 * 16;         // 98304 : 128 rows x 16 chunks
constexpr int R_AL = R_AH + 128 * 16 * 16;     // 131072
constexpr int R_SMEM = R_AL + 128 * 16 * 16;   // 163840

constexpr int I_WH = 0;                        // 64 rows x 64 chunks
constexpr int I_WL = 64 * 64 * 16;             // 65536
constexpr int I_XH = 2 * 64 * 64 * 16;         // 131072 : 128 rows x 16 chunks
constexpr int I_XL = I_XH + 128 * 16 * 16;     // 163840
constexpr int I_SMEM = I_XL + 128 * 16 * 16;   // 196608

// Device scratch
__device__ __align__(16) __half g_x_hi[(size_t)B_ * T_ * D_];
__device__ __align__(16) __half g_x_lo[(size_t)B_ * T_ * D_];
__device__ __align__(16) __half g_whh_hi[(size_t)G_ * H_];
__device__ __align__(16) __half g_whh_lo[(size_t)G_ * H_];
__device__ __align__(16) __half g_wih_hi[(size_t)G_ * D_];
__device__ __align__(16) __half g_wih_lo[(size_t)G_ * D_];
__device__ float g_IG[(size_t)T_ * B_ * G_];
__device__ __align__(16) __half g_h_hi[2][B_ * H_];
__device__ __align__(16) __half g_h_lo[2][B_ * H_];
__device__ float g_part[KS][B_ * G_];
__device__ unsigned int g_cnt;

// ---------------------------------------------------------------------------
// helpers
// ---------------------------------------------------------------------------
__device__ __forceinline__ uint32_t smem_u32(const void* p) {
    uint32_t a;
    asm("{ .reg .u64 t; cvta.to.shared.u64 t, %1; cvt.u32.u64 %0, t; }" : "=r"(a) : "l"(p));
    return a;
}
__device__ __forceinline__ void ldm4(uint32_t* r, uint32_t a) {
    asm volatile("ldmatrix.sync.aligned.m8n8.x4.shared.b16 {%0,%1,%2,%3}, [%4];"
                 : "=r"(r[0]), "=r"(r[1]), "=r"(r[2]), "=r"(r[3]) : "r"(a));
}
__device__ __forceinline__ void mma_f16(float* d, const uint32_t* a, uint32_t b0, uint32_t b1) {
    asm volatile(
        "mma.sync.aligned.m16n8k16.row.col.f32.f16.f16.f32 "
        "{%0,%1,%2,%3},{%4,%5,%6,%7},{%8,%9},{%0,%1,%2,%3};"
        : "+f"(d[0]), "+f"(d[1]), "+f"(d[2]), "+f"(d[3])
        : "r"(a[0]), "r"(a[1]), "r"(a[2]), "r"(a[3]), "r"(b0), "r"(b1));
}
__device__ __forceinline__ void sts16(uint32_t a, uint4 v) {
    asm volatile("st.shared.v4.b32 [%0], {%1,%2,%3,%4};"
                 :: "r"(a), "r"(v.x), "r"(v.y), "r"(v.z), "r"(v.w));
}
__device__ __forceinline__ void hsplit(float f, __half& hi, __half& lo) {
    hi = __float2half_rn(f);
    lo = __float2half_rn(f - __half2float(hi));
}

// ---------------------------------------------------------------------------
// init + splits
// ---------------------------------------------------------------------------
__global__ void init_kernel() {
    unsigned idx = blockIdx.x * blockDim.x + threadIdx.x;
    if (idx == 0) g_cnt = 0u;
    for (unsigned i = idx; i < (unsigned)(B_ * H_); i += gridDim.x * blockDim.x) {
        g_h_hi[0][i] = __float2half(0.0f);
        g_h_lo[0][i] = __float2half(0.0f);
    }
}
__global__ void split_w(const float* __restrict__ whh, const float* __restrict__ wih) {
    size_t i = (size_t)blockIdx.x * blockDim.x + threadIdx.x;
    size_t nhh = (size_t)G_ * H_;
    if (i < nhh) {
        __half hi, lo; hsplit(whh[i], hi, lo);
        g_whh_hi[i] = hi; g_whh_lo[i] = lo;
    } else if (i < nhh + (size_t)G_ * D_) {
        size_t j = i - nhh;
        __half hi, lo; hsplit(wih[j], hi, lo);
        g_wih_hi[j] = hi; g_wih_lo[j] = lo;
    }
}
__global__ void split_x(const float* __restrict__ x) {
    size_t i = (size_t)blockIdx.x * blockDim.x + threadIdx.x;
    size_t n2 = (size_t)B_ * T_ * D_ / 2;
    if (i < n2) {
        float2 v = reinterpret_cast<const float2*>(x)[i];
        __half h0, l0, h1, l1;
        hsplit(v.x, h0, l0); hsplit(v.y, h1, l1);
        reinterpret_cast<__half2*>(g_x_hi)[i] = __halves2half2(h0, h1);
        reinterpret_cast<__half2*>(g_x_lo)[i] = __halves2half2(l0, l1);
    }
}

// ---------------------------------------------------------------------------
// grid barrier
// ---------------------------------------------------------------------------
__device__ __forceinline__ void grid_sync(unsigned int target) {
    __threadfence();
    __syncthreads();
    if (threadIdx.x == 0) {
        atomicAdd(&g_cnt, 1u);
        while (*reinterpret_cast<volatile unsigned int*>(&g_cnt) < target) { }
    }
    __syncthreads();
}

// ---------------------------------------------------------------------------
// IG GEMM: grid (48, 256). CTA: n0 = bx*64, t = by*4 + tt.
// Warp layout 4m x 2n: warp tile 32 rows x 32 cols. K=512 in 4 chunks of 128.
// ---------------------------------------------------------------------------
__global__ __launch_bounds__(256, 1) void ig_gemm(const float* __restrict__ bias) {
    extern __shared__ __align__(1024) char smem[];
    const uint32_t sb = smem_u32(smem);
    const int tid = threadIdx.x;
    const int lane = tid & 31, warp = tid >> 5;
    const int wm = warp >> 1, wn = warp & 1;
    const int g8 = lane >> 3, r8 = lane & 7;
    const int gq = lane >> 2, cq = lane & 3;
    const int n0 = blockIdx.x * IGN;

    // ldmatrix lane rows
    int rowA[2], rowB[2];
    rowA[0] = wm * 32 + r8 + (g8 & 1) * 8; rowA[1] = rowA[0] + 16;
    rowB[0] = wn * 32 + r8 + (g8 >> 1) * 8; rowB[1] = rowB[0] + 16;
    const int cbA = g8 >> 1, cbB = g8 & 1;

    // stage W slab once: 64 rows x 64 chunks, hi+lo
    for (int idx = tid; idx < 64 * 64; idx += 256) {
        int row = idx >> 6, c = idx & 63;
        size_t src = (size_t)(n0 + row) * D_ + c * 8;
        uint32_t off = ((row * 64 + (c ^ (row & 7))) << 4);
        sts16(sb + I_WH + off, *reinterpret_cast<const uint4*>(g_wih_hi + src));
        sts16(sb + I_WL + off, *reinterpret_cast<const uint4*>(g_wih_lo + src));
    }
    __syncthreads();

    for (int tt = 0; tt < TG; tt++) {
        const int t = blockIdx.y * TG + tt;
        float acc[2][4][4];
#pragma unroll
        for (int i = 0; i < 2; i++)
#pragma unroll
            for (int j = 0; j < 4; j++)
#pragma unroll
                for (int q = 0; q < 4; q++) acc[i][j][q] = 0.0f;

        for (int kc = 0; kc < 4; kc++) {
            // stage X chunk: 128 rows x 16 chunks
            __syncthreads();
            for (int idx = tid; idx < 128 * 16; idx += 256) {
                int row = idx >> 4, c = idx & 15;
                size_t src = ((size_t)row * T_ + t) * D_ + kc * 128 + c * 8;
                uint32_t off = ((row * 16 + (c ^ (row & 7))) << 4);
                sts16(sb + I_XH + off, *reinterpret_cast<const uint4*>(g_x_hi + src));
                sts16(sb + I_XL + off, *reinterpret_cast<const uint4*>(g_x_lo + src));
            }
            __syncthreads();

#pragma unroll
            for (int kk = 0; kk < 8; kk++) {
                const int kk2 = kk * 2;
                uint32_t ah[2][4], al[2][4];
#pragma unroll
                for (int i = 0; i < 2; i++) {
                    uint32_t off = ((rowA[i] * 16 + ((kk2 + cbA) ^ (rowA[i] & 7))) << 4);
                    ldm4(ah[i], sb + I_XH + off);
                    ldm4(al[i], sb + I_XL + off);
                }
                const int kkc = kc * 16 + kk2;
                uint32_t bh[2][4], bl[2][4];
#pragma unroll
                for (int j = 0; j < 2; j++) {
                    uint32_t off = ((rowB[j] * 64 + ((kkc + cbB) ^ (rowB[j] & 7))) << 4);
                    ldm4(bh[j], sb + I_WH + off);
                    ldm4(bl[j], sb + I_WL + off);
                }
#pragma unroll
                for (int i = 0; i < 2; i++)
#pragma unroll
                    for (int j = 0; j < 2; j++) {
                        mma_f16(acc[i][2 * j],     ah[i], bh[j][0], bh[j][1]);
                        mma_f16(acc[i][2 * j + 1], ah[i], bh[j][2], bh[j][3]);
                        mma_f16(acc[i][2 * j],     ah[i], bl[j][0], bl[j][1]);
                        mma_f16(acc[i][2 * j + 1], ah[i], bl[j][2], bl[j][3]);
                        mma_f16(acc[i][2 * j],     al[i], bh[j][0], bh[j][1]);
                        mma_f16(acc[i][2 * j + 1], al[i], bh[j][2], bh[j][3]);
                    }
            }
        }

        // epilogue: bias + store
#pragma unroll
        for (int i = 0; i < 2; i++)
#pragma unroll
            for (int j = 0; j < 4; j++) {
                int row = wm * 32 + i * 16 + gq;
                int gcol = n0 + wn * 32 + j * 8 + 2 * cq;
                float b0 = __ldg(&bias[gcol]), b1 = __ldg(&bias[gcol + 1]);
                size_t o0 = ((size_t)t * B_ + row) * G_ + gcol;
                *reinterpret_cast<float2*>(&g_IG[o0]) =
                    make_float2(acc[i][j][0] + b0, acc[i][j][1] + b1);
                *reinterpret_cast<float2*>(&g_IG[o0 + (size_t)8 * G_]) =
                    make_float2(acc[i][j][2] + b0, acc[i][j][3] + b1);
            }
    }
}

// ---------------------------------------------------------------------------
// Persistent GRU recurrence. CTA (nt, ks): gate cols [nt*96, +96), k [ks*256, +256).
// Warp layout 4m x 2n: warp tile 32 rows x 48 cols. W slab persistent in smem.
// ---------------------------------------------------------------------------
__global__ __launch_bounds__(256, 1) void gru_persist(const float* __restrict__ bn) {
    extern __shared__ __align__(1024) char smem[];
    const uint32_t sb = smem_u32(smem);
    const int tid = threadIdx.x;
    const int lane = tid & 31, warp = tid >> 5;
    const int wm = warp >> 1, wn = warp & 1;
    const int g8 = lane >> 3, r8 = lane & 7;
    const int gq = lane >> 2, cq = lane & 3;

    const int nt = blockIdx.x & (NT - 1);
    const int ks = blockIdx.x >> 5;
    const int n0 = nt * NCTA;
    const int kbeg = ks * KCTA;

    int rowA[2], rowB[3];
    rowA[0] = wm * 32 + r8 + (g8 & 1) * 8; rowA[1] = rowA[0] + 16;
    rowB[0] = wn * 48 + r8 + (g8 >> 1) * 8; rowB[1] = rowB[0] + 16; rowB[2] = rowB[0] + 32;
    const int cbA = g8 >> 1, cbB = g8 & 1;

    // stage W slab once: 96 rows x 32 chunks (hi+lo)
    for (int idx = tid; idx < 96 * 32; idx += 256) {
        int row = idx >> 5, c = idx & 31;
        size_t src = (size_t)(n0 + row) * H_ + kbeg + c * 8;
        uint32_t off = ((row * 32 + (c ^ (row & 7))) << 4);
        sts16(sb + R_WH + off, *reinterpret_cast<const uint4*>(g_whh_hi + src));
        sts16(sb + R_WL + off, *reinterpret_cast<const uint4*>(g_whh_lo + src));
    }
    __syncthreads();

    unsigned round = 0;
    int cur = 0;

    for (int t = 0; t < T_; t++) {
        const __half* hhi = g_h_hi[cur];
        const __half* hlo = g_h_lo[cur];

        float acc[2][6][4];
#pragma unroll
        for (int i = 0; i < 2; i++)
#pragma unroll
            for (int j = 0; j < 6; j++)
#pragma unroll
                for (int q = 0; q < 4; q++) acc[i][j][q] = 0.0f;

        for (int kc = 0; kc < 2; kc++) {
            // stage h chunk: 128 rows x 16 chunks (cross-CTA data -> ldcg)
            for (int idx = tid; idx < 128 * 16; idx += 256) {
                int row = idx >> 4, c = idx & 15;
                size_t src = (size_t)row * H_ + kbeg + kc * 128 + c * 8;
                uint32_t off = ((row * 16 + (c ^ (row & 7))) << 4);
                sts16(sb + R_AH + off, __ldcg(reinterpret_cast<const uint4*>(hhi + src)));
                sts16(sb + R_AL + off, __ldcg(reinterpret_cast<const uint4*>(hlo + src)));
            }
            __syncthreads();

#pragma unroll
            for (int kk = 0; kk < 8; kk++) {
                const int kk2 = kk * 2;
                uint32_t ah[2][4], al[2][4];
#pragma unroll
                for (int i = 0; i < 2; i++) {
                    uint32_t off = ((rowA[i] * 16 + ((kk2 + cbA) ^ (rowA[i] & 7))) << 4);
                    ldm4(ah[i], sb + R_AH + off);
                    ldm4(al[i], sb + R_AL + off);
                }
                const int kkc = kc * 16 + kk2;
                uint32_t bh[3][4], bl[3][4];
#pragma unroll
                for (int j = 0; j < 3; j++) {
                    uint32_t off = ((rowB[j] * 32 + ((kkc + cbB) ^ (rowB[j] & 7))) << 4);
                    ldm4(bh[j], sb + R_WH + off);
                    ldm4(bl[j], sb + R_WL + off);
                }
#pragma unroll
                for (int i = 0; i < 2; i++)
#pragma unroll
                    for (int j = 0; j < 3; j++) {
                        mma_f16(acc[i][2 * j],     ah[i], bh[j][0], bh[j][1]);
                        mma_f16(acc[i][2 * j + 1], ah[i], bh[j][2], bh[j][3]);
                        mma_f16(acc[i][2 * j],     ah[i], bl[j][0], bl[j][1]);
                        mma_f16(acc[i][2 * j + 1], ah[i], bl[j][2], bl[j][3]);
                        mma_f16(acc[i][2 * j],     al[i], bh[j][0], bh[j][1]);
                        mma_f16(acc[i][2 * j + 1], al[i], bh[j][2], bh[j][3]);
                    }
            }
            __syncthreads();
        }

        // write k-split partials
#pragma unroll
        for (int i = 0; i < 2; i++)
#pragma unroll
            for (int j = 0; j < 6; j++) {
                int row = wm * 32 + i * 16 + gq;
                int gcol = n0 + wn * 48 + j * 8 + 2 * cq;
                *reinterpret_cast<float2*>(&g_part[ks][row * G_ + gcol]) =
                    make_float2(acc[i][j][0], acc[i][j][1]);
                *reinterpret_cast<float2*>(&g_part[ks][(row + 8) * G_ + gcol]) =
                    make_float2(acc[i][j][2], acc[i][j][3]);
            }

        round++; grid_sync(round * NB);

        // fused gating
        const float* ig_t = g_IG + (size_t)t * B_ * G_;
        __half* dhi = g_h_hi[cur ^ 1];
        __half* dlo = g_h_lo[cur ^ 1];
        for (int i = blockIdx.x * 256 + tid; i < B_ * H_; i += NB * 256) {
            int b = i >> 10;
            int j = i & (H_ - 1);
            int base = b * G_;
            float hgr = 0.f, hgz = 0.f, hgn = 0.f;
#pragma unroll
            for (int s = 0; s < KS; s++) {
                hgr += __ldcg(&g_part[s][base + j]);
                hgz += __ldcg(&g_part[s][base + H_ + j]);
                hgn += __ldcg(&g_part[s][base + 2 * H_ + j]);
            }
            float igr = ig_t[base + j];
            float igz = ig_t[base + H_ + j];
            float ign = ig_t[base + 2 * H_ + j];
            float hold = __half2float(__ldcg(&hhi[i])) + __half2float(__ldcg(&hlo[i]));
            float r = 1.0f / (1.0f + expf(-(igr + hgr)));
            float z = 1.0f / (1.0f + expf(-(igz + hgz)));
            float nn = tanhf(ign + r * (hgn + bn[j]));
            float hnew = nn + z * (hold - nn);
            __half hi, lo;
            hsplit(hnew, hi, lo);
            dhi[i] = hi;
            dlo[i] = lo;
        }

        round++; grid_sync(round * NB);
        cur ^= 1;
    }
}

// ---------------------------------------------------------------------------
// final projection
// ---------------------------------------------------------------------------
__global__ void out_kernel(const float* __restrict__ w_out,
                           const float* __restrict__ b_out,
                           float* __restrict__ out) {
    __shared__ float red[256];
    int b = blockIdx.x;
    float s = 0.0f;
    for (int j = threadIdx.x; j < H_; j += blockDim.x) {
        float h = __half2float(g_h_hi[0][b * H_ + j]) + __half2float(g_h_lo[0][b * H_ + j]);
        s += h * w_out[j];
    }
    red[threadIdx.x] = s;
    __syncthreads();
    for (int off = 128; off > 0; off >>= 1) {
        if (threadIdx.x < off) red[threadIdx.x] += red[threadIdx.x + off];
        __syncthreads();
    }
    if (threadIdx.x == 0) out[b] = red[0] + b_out[0];
}

// ---------------------------------------------------------------------------
extern "C" void kernel_launch(void* const* d_in, const int* in_sizes, int n_in,
                              void* d_out, int out_size) {
    const float* x     = (const float*)d_in[0];
    const float* w_ih  = (const float*)d_in[1];
    const float* w_hh  = (const float*)d_in[2];
    const float* b     = (const float*)d_in[3];
    const float* bn    = (const float*)d_in[4];
    const float* w_out = (const float*)d_in[5];
    const float* b_out = (const float*)d_in[6];
    float* out = (float*)d_out;

    cudaFuncSetAttribute(ig_gemm, cudaFuncAttributeMaxDynamicSharedMemorySize, I_SMEM);
    cudaFuncSetAttribute(gru_persist, cudaFuncAttributeMaxDynamicSharedMemorySize, R_SMEM);

    init_kernel<<<128, 256>>>();
    size_t nsplit = (size_t)G_ * H_ + (size_t)G_ * D_;
    split_w<<<(unsigned)((nsplit + 255) / 256), 256>>>(w_hh, w_ih);
    split_x<<<(unsigned)(((size_t)B_ * T_ * D_ / 2 + 255) / 256), 256>>>(x);

    dim3 gig(IGNT, T_ / TG);
    ig_gemm<<<gig, 256, I_SMEM>>>(b);

    gru_persist<<<NB, 256, R_SMEM>>>(bn);

    out_kernel<<<B_, 256>>>(w_out, b_out, out);
}

// round 5
// speedup vs baseline: 2.9737x; 1.1240x over previous
#include <cuda_runtime.h>
#include <cuda_fp16.h>
#include <cstdint>

// Problem constants
constexpr int B_ = 128;
constexpr int T_ = 1024;
constexpr int D_ = 512;
constexpr int H_ = 1024;
constexpr int G_ = 3 * H_;            // 3072

// Recurrence: 128 CTAs = NT n-tiles x KS k-splits
constexpr int NT = 32;                // 96 gate cols per CTA
constexpr int KS = 4;                 // k slice 256
constexpr int NB = NT * KS;           // 128
constexpr int NCTA = G_ / NT;         // 96
constexpr int KCTA = H_ / KS;         // 256

// IG GEMM config
constexpr int IGN  = 64;
constexpr int IGNT = G_ / IGN;        // 48
constexpr int TG   = 4;

// gru smem layout: chunk = 16B = 8 half; swizzle chunk' = chunk ^ (row&7)
// W slab: 96 rows x 32 chunks (hi, lo); h: 128 rows x 32 chunks (hi, lo)
constexpr int R_WH = 0;
constexpr int R_WL = 96 * 32 * 16;             // 49152
constexpr int R_AH = 2 * 96 * 32 * 16;         // 98304
constexpr int R_AL = R_AH + 128 * 32 * 16;     // 163840
constexpr int R_SMEM = R_AL + 128 * 32 * 16;   // 229376 (224KB)

// ig smem layout (round-4 proven)
constexpr int I_WH = 0;
constexpr int I_WL = 64 * 64 * 16;
constexpr int I_XH = 2 * 64 * 64 * 16;
constexpr int I_XL = I_XH + 128 * 16 * 16;
constexpr int I_SMEM = I_XL + 128 * 16 * 16;   // 196608

// Device scratch
__device__ __align__(16) __half g_x_hi[(size_t)B_ * T_ * D_];
__device__ __align__(16) __half g_x_lo[(size_t)B_ * T_ * D_];
__device__ __align__(16) __half g_whh_hi[(size_t)G_ * H_];
__device__ __align__(16) __half g_whh_lo[(size_t)G_ * H_];
__device__ __align__(16) __half g_wih_hi[(size_t)G_ * D_];
__device__ __align__(16) __half g_wih_lo[(size_t)G_ * D_];
__device__ float g_IG[(size_t)T_ * B_ * G_];
__device__ __align__(16) __half g_h_hi[2][B_ * H_];
__device__ __align__(16) __half g_h_lo[2][B_ * H_];
__device__ float g_part[KS][B_ * G_];
__device__ unsigned int g_flag[NB * 32];       // 128B-strided barrier flags

// ---------------------------------------------------------------------------
// helpers
// ---------------------------------------------------------------------------
__device__ __forceinline__ uint32_t smem_u32(const void* p) {
    uint32_t a;
    asm("{ .reg .u64 t; cvta.to.shared.u64 t, %1; cvt.u32.u64 %0, t; }" : "=r"(a) : "l"(p));
    return a;
}
__device__ __forceinline__ void ldm4(uint32_t* r, uint32_t a) {
    asm volatile("ldmatrix.sync.aligned.m8n8.x4.shared.b16 {%0,%1,%2,%3}, [%4];"
                 : "=r"(r[0]), "=r"(r[1]), "=r"(r[2]), "=r"(r[3]) : "r"(a));
}
__device__ __forceinline__ void mma_f16(float* d, const uint32_t* a, uint32_t b0, uint32_t b1) {
    asm volatile(
        "mma.sync.aligned.m16n8k16.row.col.f32.f16.f16.f32 "
        "{%0,%1,%2,%3},{%4,%5,%6,%7},{%8,%9},{%0,%1,%2,%3};"
        : "+f"(d[0]), "+f"(d[1]), "+f"(d[2]), "+f"(d[3])
        : "r"(a[0]), "r"(a[1]), "r"(a[2]), "r"(a[3]), "r"(b0), "r"(b1));
}
__device__ __forceinline__ void sts16(uint32_t a, uint4 v) {
    asm volatile("st.shared.v4.b32 [%0], {%1,%2,%3,%4};"
                 :: "r"(a), "r"(v.x), "r"(v.y), "r"(v.z), "r"(v.w));
}
__device__ __forceinline__ void cpa16(uint32_t s, const void* g) {
    asm volatile("cp.async.cg.shared.global [%0], [%1], 16;" :: "r"(s), "l"(g));
}
__device__ __forceinline__ void cp_commit() { asm volatile("cp.async.commit_group;" ::: "memory"); }
__device__ __forceinline__ void cp_wait0()  { asm volatile("cp.async.wait_group 0;" ::: "memory"); }
__device__ __forceinline__ void cp_wait1()  { asm volatile("cp.async.wait_group 1;" ::: "memory"); }
__device__ __forceinline__ void hsplit(float f, __half& hi, __half& lo) {
    hi = __float2half_rn(f);
    lo = __float2half_rn(f - __half2float(hi));
}

// ---------------------------------------------------------------------------
// init + splits
// ---------------------------------------------------------------------------
__global__ void init_kernel() {
    unsigned idx = blockIdx.x * blockDim.x + threadIdx.x;
    for (unsigned i = idx; i < (unsigned)(NB * 32); i += gridDim.x * blockDim.x)
        g_flag[i] = 0u;
    for (unsigned i = idx; i < (unsigned)(B_ * H_); i += gridDim.x * blockDim.x) {
        g_h_hi[0][i] = __float2half(0.0f);
        g_h_lo[0][i] = __float2half(0.0f);
    }
}
__global__ void split_w(const float* __restrict__ whh, const float* __restrict__ wih) {
    size_t i = (size_t)blockIdx.x * blockDim.x + threadIdx.x;
    size_t nhh = (size_t)G_ * H_;
    if (i < nhh) {
        __half hi, lo; hsplit(whh[i], hi, lo);
        g_whh_hi[i] = hi; g_whh_lo[i] = lo;
    } else if (i < nhh + (size_t)G_ * D_) {
        size_t j = i - nhh;
        __half hi, lo; hsplit(wih[j], hi, lo);
        g_wih_hi[j] = hi; g_wih_lo[j] = lo;
    }
}
__global__ void split_x(const float* __restrict__ x) {
    size_t i = (size_t)blockIdx.x * blockDim.x + threadIdx.x;
    size_t n2 = (size_t)B_ * T_ * D_ / 2;
    if (i < n2) {
        float2 v = reinterpret_cast<const float2*>(x)[i];
        __half h0, l0, h1, l1;
        hsplit(v.x, h0, l0); hsplit(v.y, h1, l1);
        reinterpret_cast<__half2*>(g_x_hi)[i] = __halves2half2(h0, h1);
        reinterpret_cast<__half2*>(g_x_lo)[i] = __halves2half2(l0, l1);
    }
}

// ---------------------------------------------------------------------------
// distributed-flag grid barrier: 1 release-store per CTA, parallel acquire-polls
// ---------------------------------------------------------------------------
__device__ __forceinline__ void grid_sync(unsigned int round) {
    __syncthreads();
    if (threadIdx.x == 0) {
        asm volatile("st.release.gpu.global.u32 [%0], %1;"
                     :: "l"(&g_flag[blockIdx.x * 32]), "r"(round) : "memory");
    }
    if (threadIdx.x < NB) {
        const unsigned int* p = &g_flag[threadIdx.x * 32];
        unsigned int v;
        do {
            asm volatile("ld.acquire.gpu.global.u32 %0, [%1];" : "=r"(v) : "l"(p) : "memory");
        } while (v < round);
    }
    __syncthreads();
}

// ---------------------------------------------------------------------------
// IG GEMM (round-4 proven structure): grid (48, 256)
// ---------------------------------------------------------------------------
__global__ __launch_bounds__(256, 1) void ig_gemm(const float* __restrict__ bias) {
    extern __shared__ __align__(1024) char smem[];
    const uint32_t sb = smem_u32(smem);
    const int tid = threadIdx.x;
    const int lane = tid & 31, warp = tid >> 5;
    const int wm = warp >> 1, wn = warp & 1;
    const int g8 = lane >> 3, r8 = lane & 7;
    const int gq = lane >> 2, cq = lane & 3;
    const int n0 = blockIdx.x * IGN;

    int rowA[2], rowB[2];
    rowA[0] = wm * 32 + r8 + (g8 & 1) * 8; rowA[1] = rowA[0] + 16;
    rowB[0] = wn * 32 + r8 + (g8 >> 1) * 8; rowB[1] = rowB[0] + 16;
    const int cbA = g8 >> 1, cbB = g8 & 1;

    for (int idx = tid; idx < 64 * 64; idx += 256) {
        int row = idx >> 6, c = idx & 63;
        size_t src = (size_t)(n0 + row) * D_ + c * 8;
        uint32_t off = ((row * 64 + (c ^ (row & 7))) << 4);
        cpa16(sb + I_WH + off, g_wih_hi + src);
        cpa16(sb + I_WL + off, g_wih_lo + src);
    }
    cp_commit(); cp_wait0();
    __syncthreads();

    for (int tt = 0; tt < TG; tt++) {
        const int t = blockIdx.y * TG + tt;
        float acc[2][4][4];
#pragma unroll
        for (int i = 0; i < 2; i++)
#pragma unroll
            for (int j = 0; j < 4; j++)
#pragma unroll
                for (int q = 0; q < 4; q++) acc[i][j][q] = 0.0f;

        for (int kc = 0; kc < 4; kc++) {
            __syncthreads();
            for (int idx = tid; idx < 128 * 16; idx += 256) {
                int row = idx >> 4, c = idx & 15;
                size_t src = ((size_t)row * T_ + t) * D_ + kc * 128 + c * 8;
                uint32_t off = ((row * 16 + (c ^ (row & 7))) << 4);
                cpa16(sb + I_XH + off, g_x_hi + src);
                cpa16(sb + I_XL + off, g_x_lo + src);
            }
            cp_commit(); cp_wait0();
            __syncthreads();

#pragma unroll
            for (int kk = 0; kk < 8; kk++) {
                const int kk2 = kk * 2;
                uint32_t ah[2][4], al[2][4];
#pragma unroll
                for (int i = 0; i < 2; i++) {
                    uint32_t off = ((rowA[i] * 16 + ((kk2 + cbA) ^ (rowA[i] & 7))) << 4);
                    ldm4(ah[i], sb + I_XH + off);
                    ldm4(al[i], sb + I_XL + off);
                }
                const int kkc = kc * 16 + kk2;
                uint32_t bh[2][4], bl[2][4];
#pragma unroll
                for (int j = 0; j < 2; j++) {
                    uint32_t off = ((rowB[j] * 64 + ((kkc + cbB) ^ (rowB[j] & 7))) << 4);
                    ldm4(bh[j], sb + I_WH + off);
                    ldm4(bl[j], sb + I_WL + off);
                }
#pragma unroll
                for (int i = 0; i < 2; i++)
#pragma unroll
                    for (int j = 0; j < 2; j++) {
                        mma_f16(acc[i][2 * j],     ah[i], bh[j][0], bh[j][1]);
                        mma_f16(acc[i][2 * j + 1], ah[i], bh[j][2], bh[j][3]);
                        mma_f16(acc[i][2 * j],     ah[i], bl[j][0], bl[j][1]);
                        mma_f16(acc[i][2 * j + 1], ah[i], bl[j][2], bl[j][3]);
                        mma_f16(acc[i][2 * j],     al[i], bh[j][0], bh[j][1]);
                        mma_f16(acc[i][2 * j + 1], al[i], bh[j][2], bh[j][3]);
                    }
            }
        }

#pragma unroll
        for (int i = 0; i < 2; i++)
#pragma unroll
            for (int j = 0; j < 4; j++) {
                int row = wm * 32 + i * 16 + gq;
                int gcol = n0 + wn * 32 + j * 8 + 2 * cq;
                float b0 = __ldg(&bias[gcol]), b1 = __ldg(&bias[gcol + 1]);
                size_t o0 = ((size_t)t * B_ + row) * G_ + gcol;
                *reinterpret_cast<float2*>(&g_IG[o0]) =
                    make_float2(acc[i][j][0] + b0, acc[i][j][1] + b1);
                *reinterpret_cast<float2*>(&g_IG[o0 + (size_t)8 * G_]) =
                    make_float2(acc[i][j][2] + b0, acc[i][j][3] + b1);
            }
    }
}

// ---------------------------------------------------------------------------
// Persistent GRU recurrence. W slab persistent in smem; whole 256-k h slice
// staged per step via cp.async in 2 pipelined halves.
// ---------------------------------------------------------------------------
__global__ __launch_bounds__(256, 1) void gru_persist(const float* __restrict__ bn) {
    extern __shared__ __align__(1024) char smem[];
    const uint32_t sb = smem_u32(smem);
    const int tid = threadIdx.x;
    const int lane = tid & 31, warp = tid >> 5;
    const int wm = warp >> 1, wn = warp & 1;
    const int g8 = lane >> 3, r8 = lane & 7;
    const int gq = lane >> 2, cq = lane & 3;

    const int nt = blockIdx.x & (NT - 1);
    const int ks = blockIdx.x >> 5;
    const int n0 = nt * NCTA;
    const int kbeg = ks * KCTA;

    int rowA[2], rowB[3];
    rowA[0] = wm * 32 + r8 + (g8 & 1) * 8; rowA[1] = rowA[0] + 16;
    rowB[0] = wn * 48 + r8 + (g8 >> 1) * 8; rowB[1] = rowB[0] + 16; rowB[2] = rowB[0] + 32;
    const int cbA = g8 >> 1, cbB = g8 & 1;

    // stage W slab once: 96 rows x 32 chunks (hi+lo)
    for (int idx = tid; idx < 96 * 32; idx += 256) {
        int row = idx >> 5, c = idx & 31;
        size_t src = (size_t)(n0 + row) * H_ + kbeg + c * 8;
        uint32_t off = ((row * 32 + (c ^ (row & 7))) << 4);
        cpa16(sb + R_WH + off, g_whh_hi + src);
        cpa16(sb + R_WL + off, g_whh_lo + src);
    }
    cp_commit(); cp_wait0();
    __syncthreads();

    unsigned round = 0;
    int cur = 0;

    for (int t = 0; t < T_; t++) {
        const __half* hhi = g_h_hi[cur];
        const __half* hlo = g_h_lo[cur];

        // stage h slice in 2 halves (chunks 0..15, 16..31), pipelined
#pragma unroll
        for (int hf = 0; hf < 2; hf++) {
#pragma unroll
            for (int i = 0; i < 8; i++) {
                int e = tid + i * 256;            // 2048 = 128 rows x 16 chunks
                int row = e >> 4, c = (e & 15) + hf * 16;
                size_t src = (size_t)row * H_ + kbeg + c * 8;
                uint32_t off = ((row * 32 + (c ^ (row & 7))) << 4);
                cpa16(sb + R_AH + off, hhi + src);
                cpa16(sb + R_AL + off, hlo + src);
            }
            cp_commit();
        }

        float acc[2][6][4];
#pragma unroll
        for (int i = 0; i < 2; i++)
#pragma unroll
            for (int j = 0; j < 6; j++)
#pragma unroll
                for (int q = 0; q < 4; q++) acc[i][j][q] = 0.0f;

#pragma unroll
        for (int hf = 0; hf < 2; hf++) {
            if (hf == 0) cp_wait1(); else cp_wait0();
            __syncthreads();
#pragma unroll
            for (int kk = 0; kk < 8; kk++) {
                const int kk2 = hf * 16 + kk * 2;
                uint32_t ah[2][4], al[2][4];
#pragma unroll
                for (int i = 0; i < 2; i++) {
                    uint32_t off = ((rowA[i] * 32 + ((kk2 + cbA) ^ (rowA[i] & 7))) << 4);
                    ldm4(ah[i], sb + R_AH + off);
                    ldm4(al[i], sb + R_AL + off);
                }
                uint32_t bh[3][4], bl[3][4];
#pragma unroll
                for (int j = 0; j < 3; j++) {
                    uint32_t off = ((rowB[j] * 32 + ((kk2 + cbB) ^ (rowB[j] & 7))) << 4);
                    ldm4(bh[j], sb + R_WH + off);
                    ldm4(bl[j], sb + R_WL + off);
                }
#pragma unroll
                for (int i = 0; i < 2; i++)
#pragma unroll
                    for (int j = 0; j < 3; j++) {
                        mma_f16(acc[i][2 * j],     ah[i], bh[j][0], bh[j][1]);
                        mma_f16(acc[i][2 * j + 1], ah[i], bh[j][2], bh[j][3]);
                        mma_f16(acc[i][2 * j],     ah[i], bl[j][0], bl[j][1]);
                        mma_f16(acc[i][2 * j + 1], ah[i], bl[j][2], bl[j][3]);
                        mma_f16(acc[i][2 * j],     al[i], bh[j][0], bh[j][1]);
                        mma_f16(acc[i][2 * j + 1], al[i], bh[j][2], bh[j][3]);
                    }
            }
        }

        // write k-split partials
#pragma unroll
        for (int i = 0; i < 2; i++)
#pragma unroll
            for (int j = 0; j < 6; j++) {
                int row = wm * 32 + i * 16 + gq;
                int gcol = n0 + wn * 48 + j * 8 + 2 * cq;
                *reinterpret_cast<float2*>(&g_part[ks][row * G_ + gcol]) =
                    make_float2(acc[i][j][0], acc[i][j][1]);
                *reinterpret_cast<float2*>(&g_part[ks][(row + 8) * G_ + gcol]) =
                    make_float2(acc[i][j][2], acc[i][j][3]);
            }

        round++; grid_sync(round);

        // fused gating
        const float* ig_t = g_IG + (size_t)t * B_ * G_;
        __half* dhi = g_h_hi[cur ^ 1];
        __half* dlo = g_h_lo[cur ^ 1];
        for (int i = blockIdx.x * 256 + tid; i < B_ * H_; i += NB * 256) {
            int b = i >> 10;
            int j = i & (H_ - 1);
            int base = b * G_;
            float hgr = 0.f, hgz = 0.f, hgn = 0.f;
#pragma unroll
            for (int s = 0; s < KS; s++) {
                hgr += __ldcg(&g_part[s][base + j]);
                hgz += __ldcg(&g_part[s][base + H_ + j]);
                hgn += __ldcg(&g_part[s][base + 2 * H_ + j]);
            }
            float igr = ig_t[base + j];
            float igz = ig_t[base + H_ + j];
            float ign = ig_t[base + 2 * H_ + j];
            float hold = __half2float(__ldcg(&hhi[i])) + __half2float(__ldcg(&hlo[i]));
            float r = 1.0f / (1.0f + expf(-(igr + hgr)));
            float z = 1.0f / (1.0f + expf(-(igz + hgz)));
            float nn = tanhf(ign + r * (hgn + bn[j]));
            float hnew = nn + z * (hold - nn);
            __half hi, lo;
            hsplit(hnew, hi, lo);
            dhi[i] = hi;
            dlo[i] = lo;
        }

        round++; grid_sync(round);
        cur ^= 1;
    }
}

// ---------------------------------------------------------------------------
// final projection
// ---------------------------------------------------------------------------
__global__ void out_kernel(const float* __restrict__ w_out,
                           const float* __restrict__ b_out,
                           float* __restrict__ out) {
    __shared__ float red[256];
    int b = blockIdx.x;
    float s = 0.0f;
    for (int j = threadIdx.x; j < H_; j += blockDim.x) {
        float h = __half2float(g_h_hi[0][b * H_ + j]) + __half2float(g_h_lo[0][b * H_ + j]);
        s += h * w_out[j];
    }
    red[threadIdx.x] = s;
    __syncthreads();
    for (int off = 128; off > 0; off >>= 1) {
        if (threadIdx.x < off) red[threadIdx.x] += red[threadIdx.x + off];
        __syncthreads();
    }
    if (threadIdx.x == 0) out[b] = red[0] + b_out[0];
}

// ---------------------------------------------------------------------------
extern "C" void kernel_launch(void* const* d_in, const int* in_sizes, int n_in,
                              void* d_out, int out_size) {
    const float* x     = (const float*)d_in[0];
    const float* w_ih  = (const float*)d_in[1];
    const float* w_hh  = (const float*)d_in[2];
    const float* b     = (const float*)d_in[3];
    const float* bn    = (const float*)d_in[4];
    const float* w_out = (const float*)d_in[5];
    const float* b_out = (const float*)d_in[6];
    float* out = (float*)d_out;

    cudaFuncSetAttribute(ig_gemm, cudaFuncAttributeMaxDynamicSharedMemorySize, I_SMEM);
    cudaFuncSetAttribute(gru_persist, cudaFuncAttributeMaxDynamicSharedMemorySize, R_SMEM);

    init_kernel<<<128, 256>>>();
    size_t nsplit = (size_t)G_ * H_ + (size_t)G_ * D_;
    split_w<<<(unsigned)((nsplit + 255) / 256), 256>>>(w_hh, w_ih);
    split_x<<<(unsigned)(((size_t)B_ * T_ * D_ / 2 + 255) / 256), 256>>>(x);

    dim3 gig(IGNT, T_ / TG);
    ig_gemm<<<gig, 256, I_SMEM>>>(b);

    gru_persist<<<NB, 256, R_SMEM>>>(bn);

    out_kernel<<<B_, 256>>>(w_out, b_out, out);
}

// round 6
// speedup vs baseline: 3.3524x; 1.1273x over previous
#include <cuda_runtime.h>
#include <cuda_fp16.h>
#include <cstdint>

// Problem constants
constexpr int B_ = 128;
constexpr int T_ = 1024;
constexpr int D_ = 512;
constexpr int H_ = 1024;
constexpr int G_ = 3 * H_;            // 3072

// Recurrence: 128 CTAs = NT h-col tiles x KS k-splits, gate-aligned tiles
constexpr int NT = 32;                // 32 h-cols per tile -> 96 gate cols (3 gates)
constexpr int KS = 4;                 // k slice 256
constexpr int NB = NT * KS;           // 128
constexpr int KCTA = H_ / KS;         // 256

// IG GEMM config (round-5 proven, unchanged)
constexpr int IGN  = 64;
constexpr int IGNT = G_ / IGN;        // 48
constexpr int TG   = 4;

// gru smem layout: chunk = 16B = 8 half; swizzle chunk' = chunk ^ (row&7)
constexpr int R_WH = 0;                        // 96 rows x 32 chunks
constexpr int R_WL = 96 * 32 * 16;             // 49152
constexpr int R_AH = 2 * 96 * 32 * 16;         // 98304 : 128 rows x 32 chunks
constexpr int R_AL = R_AH + 128 * 32 * 16;     // 163840
constexpr int R_SMEM = R_AL + 128 * 32 * 16;   // 229376 (224KB)

// ig smem layout
constexpr int I_WH = 0;
constexpr int I_WL = 64 * 64 * 16;
constexpr int I_XH = 2 * 64 * 64 * 16;
constexpr int I_XL = I_XH + 128 * 16 * 16;
constexpr int I_SMEM = I_XL + 128 * 16 * 16;   // 196608

// Device scratch
__device__ __align__(16) __half g_x_hi[(size_t)B_ * T_ * D_];
__device__ __align__(16) __half g_x_lo[(size_t)B_ * T_ * D_];
__device__ __align__(16) __half g_whh_hi[(size_t)G_ * H_];
__device__ __align__(16) __half g_whh_lo[(size_t)G_ * H_];
__device__ __align__(16) __half g_wih_hi[(size_t)G_ * D_];
__device__ __align__(16) __half g_wih_lo[(size_t)G_ * D_];
__device__ float g_IG[(size_t)T_ * B_ * G_];
__device__ __align__(16) __half g_h_hi[2][B_ * H_];
__device__ __align__(16) __half g_h_lo[2][B_ * H_];
__device__ __align__(16) float g_part[(size_t)NT * KS * 128 * 96];   // [nt][ks][row][96]
__device__ unsigned int g_Pf[NT][KS][32];      // partials-ready flags (128B strided)
__device__ unsigned int g_Hf[NT][KS][32];      // h-chunk-ready flags

// ---------------------------------------------------------------------------
// helpers
// ---------------------------------------------------------------------------
__device__ __forceinline__ uint32_t smem_u32(const void* p) {
    uint32_t a;
    asm("{ .reg .u64 t; cvta.to.shared.u64 t, %1; cvt.u32.u64 %0, t; }" : "=r"(a) : "l"(p));
    return a;
}
__device__ __forceinline__ void ldm4(uint32_t* r, uint32_t a) {
    asm volatile("ldmatrix.sync.aligned.m8n8.x4.shared.b16 {%0,%1,%2,%3}, [%4];"
                 : "=r"(r[0]), "=r"(r[1]), "=r"(r[2]), "=r"(r[3]) : "r"(a));
}
__device__ __forceinline__ void mma_f16(float* d, const uint32_t* a, uint32_t b0, uint32_t b1) {
    asm volatile(
        "mma.sync.aligned.m16n8k16.row.col.f32.f16.f16.f32 "
        "{%0,%1,%2,%3},{%4,%5,%6,%7},{%8,%9},{%0,%1,%2,%3};"
        : "+f"(d[0]), "+f"(d[1]), "+f"(d[2]), "+f"(d[3])
        : "r"(a[0]), "r"(a[1]), "r"(a[2]), "r"(a[3]), "r"(b0), "r"(b1));
}
__device__ __forceinline__ void cpa16(uint32_t s, const void* g) {
    asm volatile("cp.async.cg.shared.global [%0], [%1], 16;" :: "r"(s), "l"(g));
}
__device__ __forceinline__ void cp_commit() { asm volatile("cp.async.commit_group;" ::: "memory"); }
__device__ __forceinline__ void cp_wait0()  { asm volatile("cp.async.wait_group 0;" ::: "memory"); }
__device__ __forceinline__ void cp_wait1()  { asm volatile("cp.async.wait_group 1;" ::: "memory"); }
__device__ __forceinline__ void hsplit(float f, __half& hi, __half& lo) {
    hi = __float2half_rn(f);
    lo = __float2half_rn(f - __half2float(hi));
}
__device__ __forceinline__ void poll_ge(const unsigned int* p, unsigned int v) {
    unsigned int x;
    do {
        asm volatile("ld.acquire.gpu.global.u32 %0, [%1];" : "=r"(x) : "l"(p) : "memory");
    } while (x < v);
}
__device__ __forceinline__ void rel_st(unsigned int* p, unsigned int v) {
    asm volatile("st.release.gpu.global.u32 [%0], %1;" :: "l"(p), "r"(v) : "memory");
}

// ---------------------------------------------------------------------------
// init + splits
// ---------------------------------------------------------------------------
__global__ void init_kernel() {
    unsigned idx = blockIdx.x * blockDim.x + threadIdx.x;
    unsigned nflags = NT * KS * 32;
    for (unsigned i = idx; i < nflags; i += gridDim.x * blockDim.x) {
        (&g_Pf[0][0][0])[i] = 0u;
        (&g_Hf[0][0][0])[i] = 0u;
    }
    for (unsigned i = idx; i < (unsigned)(B_ * H_); i += gridDim.x * blockDim.x) {
        g_h_hi[0][i] = __float2half(0.0f);
        g_h_lo[0][i] = __float2half(0.0f);
    }
}
__global__ void split_w(const float* __restrict__ whh, const float* __restrict__ wih) {
    size_t i = (size_t)blockIdx.x * blockDim.x + threadIdx.x;
    size_t nhh = (size_t)G_ * H_;
    if (i < nhh) {
        __half hi, lo; hsplit(whh[i], hi, lo);
        g_whh_hi[i] = hi; g_whh_lo[i] = lo;
    } else if (i < nhh + (size_t)G_ * D_) {
        size_t j = i - nhh;
        __half hi, lo; hsplit(wih[j], hi, lo);
        g_wih_hi[j] = hi; g_wih_lo[j] = lo;
    }
}
__global__ void split_x(const float* __restrict__ x) {
    size_t i = (size_t)blockIdx.x * blockDim.x + threadIdx.x;
    size_t n2 = (size_t)B_ * T_ * D_ / 2;
    if (i < n2) {
        float2 v = reinterpret_cast<const float2*>(x)[i];
        __half h0, l0, h1, l1;
        hsplit(v.x, h0, l0); hsplit(v.y, h1, l1);
        reinterpret_cast<__half2*>(g_x_hi)[i] = __halves2half2(h0, h1);
        reinterpret_cast<__half2*>(g_x_lo)[i] = __halves2half2(l0, l1);
    }
}

// ---------------------------------------------------------------------------
// IG GEMM (round-5 proven, unchanged): grid (48, 256)
// ---------------------------------------------------------------------------
__global__ __launch_bounds__(256, 1) void ig_gemm(const float* __restrict__ bias) {
    extern __shared__ __align__(1024) char smem[];
    const uint32_t sb = smem_u32(smem);
    const int tid = threadIdx.x;
    const int lane = tid & 31, warp = tid >> 5;
    const int wm = warp >> 1, wn = warp & 1;
    const int g8 = lane >> 3, r8 = lane & 7;
    const int gq = lane >> 2, cq = lane & 3;
    const int n0 = blockIdx.x * IGN;

    int rowA[2], rowB[2];
    rowA[0] = wm * 32 + r8 + (g8 & 1) * 8; rowA[1] = rowA[0] + 16;
    rowB[0] = wn * 32 + r8 + (g8 >> 1) * 8; rowB[1] = rowB[0] + 16;
    const int cbA = g8 >> 1, cbB = g8 & 1;

    for (int idx = tid; idx < 64 * 64; idx += 256) {
        int row = idx >> 6, c = idx & 63;
        size_t src = (size_t)(n0 + row) * D_ + c * 8;
        uint32_t off = ((row * 64 + (c ^ (row & 7))) << 4);
        cpa16(sb + I_WH + off, g_wih_hi + src);
        cpa16(sb + I_WL + off, g_wih_lo + src);
    }
    cp_commit(); cp_wait0();
    __syncthreads();

    for (int tt = 0; tt < TG; tt++) {
        const int t = blockIdx.y * TG + tt;
        float acc[2][4][4];
#pragma unroll
        for (int i = 0; i < 2; i++)
#pragma unroll
            for (int j = 0; j < 4; j++)
#pragma unroll
                for (int q = 0; q < 4; q++) acc[i][j][q] = 0.0f;

        for (int kc = 0; kc < 4; kc++) {
            __syncthreads();
            for (int idx = tid; idx < 128 * 16; idx += 256) {
                int row = idx >> 4, c = idx & 15;
                size_t src = ((size_t)row * T_ + t) * D_ + kc * 128 + c * 8;
                uint32_t off = ((row * 16 + (c ^ (row & 7))) << 4);
                cpa16(sb + I_XH + off, g_x_hi + src);
                cpa16(sb + I_XL + off, g_x_lo + src);
            }
            cp_commit(); cp_wait0();
            __syncthreads();

#pragma unroll
            for (int kk = 0; kk < 8; kk++) {
                const int kk2 = kk * 2;
                uint32_t ah[2][4], al[2][4];
#pragma unroll
                for (int i = 0; i < 2; i++) {
                    uint32_t off = ((rowA[i] * 16 + ((kk2 + cbA) ^ (rowA[i] & 7))) << 4);
                    ldm4(ah[i], sb + I_XH + off);
                    ldm4(al[i], sb + I_XL + off);
                }
                const int kkc = kc * 16 + kk2;
                uint32_t bh[2][4], bl[2][4];
#pragma unroll
                for (int j = 0; j < 2; j++) {
                    uint32_t off = ((rowB[j] * 64 + ((kkc + cbB) ^ (rowB[j] & 7))) << 4);
                    ldm4(bh[j], sb + I_WH + off);
                    ldm4(bl[j], sb + I_WL + off);
                }
#pragma unroll
                for (int i = 0; i < 2; i++)
#pragma unroll
                    for (int j = 0; j < 2; j++) {
                        mma_f16(acc[i][2 * j],     ah[i], bh[j][0], bh[j][1]);
                        mma_f16(acc[i][2 * j + 1], ah[i], bh[j][2], bh[j][3]);
                        mma_f16(acc[i][2 * j],     ah[i], bl[j][0], bl[j][1]);
                        mma_f16(acc[i][2 * j + 1], ah[i], bl[j][2], bl[j][3]);
                        mma_f16(acc[i][2 * j],     al[i], bh[j][0], bh[j][1]);
                        mma_f16(acc[i][2 * j + 1], al[i], bh[j][2], bh[j][3]);
                    }
            }
        }

#pragma unroll
        for (int i = 0; i < 2; i++)
#pragma unroll
            for (int j = 0; j < 4; j++) {
                int row = wm * 32 + i * 16 + gq;
                int gcol = n0 + wn * 32 + j * 8 + 2 * cq;
                float b0 = __ldg(&bias[gcol]), b1 = __ldg(&bias[gcol + 1]);
                size_t o0 = ((size_t)t * B_ + row) * G_ + gcol;
                *reinterpret_cast<float2*>(&g_IG[o0]) =
                    make_float2(acc[i][j][0] + b0, acc[i][j][1] + b1);
                *reinterpret_cast<float2*>(&g_IG[o0 + (size_t)8 * G_]) =
                    make_float2(acc[i][j][2] + b0, acc[i][j][3] + b1);
            }
    }
}

// ---------------------------------------------------------------------------
// Persistent GRU recurrence with fine-grained flag sync.
// CTA (nt, ks): h-cols [nt*32, +32) x 3 gates (96 gate cols), k [ks*256, +256).
// Gating: rows [ks*32, +32) x its own 32 h-cols (fully tile-local partials).
// ---------------------------------------------------------------------------
__global__ __launch_bounds__(256, 1) void gru_persist(const float* __restrict__ bn) {
    extern __shared__ __align__(1024) char smem[];
    const uint32_t sb = smem_u32(smem);
    const int tid = threadIdx.x;
    const int lane = tid & 31, warp = tid >> 5;
    const int wm = warp >> 1, wn = warp & 1;
    const int g8 = lane >> 3, r8 = lane & 7;
    const int gq = lane >> 2, cq = lane & 3;

    const int nt = blockIdx.x & (NT - 1);
    const int ks = blockIdx.x >> 5;
    const int kbeg = ks * KCTA;

    int rowA[2], rowB[3];
    rowA[0] = wm * 32 + r8 + (g8 & 1) * 8; rowA[1] = rowA[0] + 16;
    rowB[0] = wn * 48 + r8 + (g8 >> 1) * 8; rowB[1] = rowB[0] + 16; rowB[2] = rowB[0] + 32;
    const int cbA = g8 >> 1, cbB = g8 & 1;

    // stage W slab once: slab row nc (0..95) <- w_hh[(nc/32)*H + nt*32 + nc%32]
    for (int idx = tid; idx < 96 * 32; idx += 256) {
        int nc = idx >> 5, c = idx & 31;
        int wrow = (nc >> 5) * H_ + nt * 32 + (nc & 31);
        size_t src = (size_t)wrow * H_ + kbeg + c * 8;
        uint32_t off = ((nc * 32 + (c ^ (nc & 7))) << 4);
        cpa16(sb + R_WH + off, g_whh_hi + src);
        cpa16(sb + R_WL + off, g_whh_lo + src);
    }
    cp_commit(); cp_wait0();
    __syncthreads();

    // gating thread mapping
    const int grl = tid >> 3;                 // 0..31 local row
    const int gc  = (tid & 7) * 4;            // 0..28 local col (x4)
    const int hc  = nt * 32 + gc;

    float* mypart = g_part + ((size_t)(nt * KS + ks) * 128) * 96;

    for (int t = 0; t < T_; t++) {
        // ---- dependency waits (merged, one sync) ----
        if (tid < 32) {
            // staging deps: h cols for k-slice [ks*256,+256) ready at step t
            poll_ge(&g_Hf[ks * 8 + (tid >> 2)][tid & 3][0], (unsigned)t);
        } else if (tid < 36) {
            // partial-buffer WAR: gating(t-1) of own nt finished reading partials(t-1)
            poll_ge(&g_Hf[nt][tid - 32][0], (unsigned)t);
        }
        __syncthreads();

        const __half* hhi = g_h_hi[t & 1];
        const __half* hlo = g_h_lo[t & 1];

        // ---- stage h slice (2 pipelined halves) ----
#pragma unroll
        for (int hf = 0; hf < 2; hf++) {
#pragma unroll
            for (int i = 0; i < 8; i++) {
                int e = tid + i * 256;
                int row = e >> 4, c = (e & 15) + hf * 16;
                size_t src = (size_t)row * H_ + kbeg + c * 8;
                uint32_t off = ((row * 32 + (c ^ (row & 7))) << 4);
                cpa16(sb + R_AH + off, hhi + src);
                cpa16(sb + R_AL + off, hlo + src);
            }
            cp_commit();
        }

        float acc[2][6][4];
#pragma unroll
        for (int i = 0; i < 2; i++)
#pragma unroll
            for (int j = 0; j < 6; j++)
#pragma unroll
                for (int q = 0; q < 4; q++) acc[i][j][q] = 0.0f;

#pragma unroll
        for (int hf = 0; hf < 2; hf++) {
            if (hf == 0) cp_wait1(); else cp_wait0();
            __syncthreads();
#pragma unroll
            for (int kk = 0; kk < 8; kk++) {
                const int kk2 = hf * 16 + kk * 2;
                uint32_t ah[2][4], al[2][4];
#pragma unroll
                for (int i = 0; i < 2; i++) {
                    uint32_t off = ((rowA[i] * 32 + ((kk2 + cbA) ^ (rowA[i] & 7))) << 4);
                    ldm4(ah[i], sb + R_AH + off);
                    ldm4(al[i], sb + R_AL + off);
                }
                uint32_t bh[3][4], bl[3][4];
#pragma unroll
                for (int j = 0; j < 3; j++) {
                    uint32_t off = ((rowB[j] * 32 + ((kk2 + cbB) ^ (rowB[j] & 7))) << 4);
                    ldm4(bh[j], sb + R_WH + off);
                    ldm4(bl[j], sb + R_WL + off);
                }
#pragma unroll
                for (int i = 0; i < 2; i++)
#pragma unroll
                    for (int j = 0; j < 3; j++) {
                        mma_f16(acc[i][2 * j],     ah[i], bh[j][0], bh[j][1]);
                        mma_f16(acc[i][2 * j + 1], ah[i], bh[j][2], bh[j][3]);
                        mma_f16(acc[i][2 * j],     ah[i], bl[j][0], bl[j][1]);
                        mma_f16(acc[i][2 * j + 1], ah[i], bl[j][2], bl[j][3]);
                        mma_f16(acc[i][2 * j],     al[i], bh[j][0], bh[j][1]);
                        mma_f16(acc[i][2 * j + 1], al[i], bh[j][2], bh[j][3]);
                    }
            }
        }

        // ---- store partials (tile-local layout [row][96]) ----
#pragma unroll
        for (int i = 0; i < 2; i++)
#pragma unroll
            for (int j = 0; j < 6; j++) {
                int row = wm * 32 + i * 16 + gq;
                int nc  = wn * 48 + j * 8 + 2 * cq;
                *reinterpret_cast<float2*>(mypart + (size_t)row * 96 + nc) =
                    make_float2(acc[i][j][0], acc[i][j][1]);
                *reinterpret_cast<float2*>(mypart + (size_t)(row + 8) * 96 + nc) =
                    make_float2(acc[i][j][2], acc[i][j][3]);
            }
        __syncthreads();
        if (tid == 0) rel_st(&g_Pf[nt][ks][0], (unsigned)(t + 1));

        // ---- gating wait: partials from all 4 k-splits of own nt ----
        if (tid < 4) poll_ge(&g_Pf[nt][tid][0], (unsigned)(t + 1));
        __syncthreads();

        // ---- gating: rows [ks*32,+32) x 32 own h-cols ----
        {
            const int grow = ks * 32 + grl;
            float4 pr = make_float4(0.f, 0.f, 0.f, 0.f), pz = pr, pn = pr;
#pragma unroll
            for (int s = 0; s < KS; s++) {
                const float* pp = g_part + ((size_t)(nt * KS + s) * 128 + grow) * 96;
                float4 a = __ldcg(reinterpret_cast<const float4*>(pp + gc));
                float4 bz = __ldcg(reinterpret_cast<const float4*>(pp + 32 + gc));
                float4 cn = __ldcg(reinterpret_cast<const float4*>(pp + 64 + gc));
                pr.x += a.x;  pr.y += a.y;  pr.z += a.z;  pr.w += a.w;
                pz.x += bz.x; pz.y += bz.y; pz.z += bz.z; pz.w += bz.w;
                pn.x += cn.x; pn.y += cn.y; pn.z += cn.z; pn.w += cn.w;
            }
            const float* ig_t = g_IG + ((size_t)t * B_ + grow) * G_;
            float4 igr = *reinterpret_cast<const float4*>(ig_t + hc);
            float4 igz = *reinterpret_cast<const float4*>(ig_t + H_ + hc);
            float4 ign = *reinterpret_cast<const float4*>(ig_t + 2 * H_ + hc);
            float4 bnv = *reinterpret_cast<const float4*>(bn + hc);

            int hidx = grow * H_ + hc;
            const __half2* phh = reinterpret_cast<const __half2*>(&hhi[hidx]);
            const __half2* phl = reinterpret_cast<const __half2*>(&hlo[hidx]);
            float2 hh0 = __half22float2(phh[0]), hh1 = __half22float2(phh[1]);
            float2 hl0 = __half22float2(phl[0]), hl1 = __half22float2(phl[1]);

            float hold[4] = { hh0.x + hl0.x, hh0.y + hl0.y, hh1.x + hl1.x, hh1.y + hl1.y };
            float hgr[4] = { pr.x, pr.y, pr.z, pr.w };
            float hgz[4] = { pz.x, pz.y, pz.z, pz.w };
            float hgn[4] = { pn.x, pn.y, pn.z, pn.w };
            float igrv[4] = { igr.x, igr.y, igr.z, igr.w };
            float igzv[4] = { igz.x, igz.y, igz.z, igz.w };
            float ignv[4] = { ign.x, ign.y, ign.z, ign.w };
            float bnvv[4] = { bnv.x, bnv.y, bnv.z, bnv.w };

            __half nhi[4], nlo[4];
#pragma unroll
            for (int q = 0; q < 4; q++) {
                float r = 1.0f / (1.0f + expf(-(igrv[q] + hgr[q])));
                float z = 1.0f / (1.0f + expf(-(igzv[q] + hgz[q])));
                float nn = tanhf(ignv[q] + r * (hgn[q] + bnvv[q]));
                float hnew = nn + z * (hold[q] - nn);
                hsplit(hnew, nhi[q], nlo[q]);
            }
            __half2* dhh = reinterpret_cast<__half2*>(&g_h_hi[(t + 1) & 1][hidx]);
            __half2* dhl = reinterpret_cast<__half2*>(&g_h_lo[(t + 1) & 1][hidx]);
            dhh[0] = __halves2half2(nhi[0], nhi[1]);
            dhh[1] = __halves2half2(nhi[2], nhi[3]);
            dhl[0] = __halves2half2(nlo[0], nlo[1]);
            dhl[1] = __halves2half2(nlo[2], nlo[3]);
        }
        __syncthreads();
        if (tid == 0) rel_st(&g_Hf[nt][ks][0], (unsigned)(t + 1));
    }
}

// ---------------------------------------------------------------------------
// final projection
// ---------------------------------------------------------------------------
__global__ void out_kernel(const float* __restrict__ w_out,
                           const float* __restrict__ b_out,
                           float* __restrict__ out) {
    __shared__ float red[256];
    int b = blockIdx.x;
    float s = 0.0f;
    for (int j = threadIdx.x; j < H_; j += blockDim.x) {
        float h = __half2float(g_h_hi[0][b * H_ + j]) + __half2float(g_h_lo[0][b * H_ + j]);
        s += h * w_out[j];
    }
    red[threadIdx.x] = s;
    __syncthreads();
    for (int off = 128; off > 0; off >>= 1) {
        if (threadIdx.x < off) red[threadIdx.x] += red[threadIdx.x + off];
        __syncthreads();
    }
    if (threadIdx.x == 0) out[b] = red[0] + b_out[0];
}

// ---------------------------------------------------------------------------
extern "C" void kernel_launch(void* const* d_in, const int* in_sizes, int n_in,
                              void* d_out, int out_size) {
    const float* x     = (const float*)d_in[0];
    const float* w_ih  = (const float*)d_in[1];
    const float* w_hh  = (const float*)d_in[2];
    const float* b     = (const float*)d_in[3];
    const float* bn    = (const float*)d_in[4];
    const float* w_out = (const float*)d_in[5];
    const float* b_out = (const float*)d_in[6];
    float* out = (float*)d_out;

    cudaFuncSetAttribute(ig_gemm, cudaFuncAttributeMaxDynamicSharedMemorySize, I_SMEM);
    cudaFuncSetAttribute(gru_persist, cudaFuncAttributeMaxDynamicSharedMemorySize, R_SMEM);

    init_kernel<<<128, 256>>>();
    size_t nsplit = (size_t)G_ * H_ + (size_t)G_ * D_;
    split_w<<<(unsigned)((nsplit + 255) / 256), 256>>>(w_hh, w_ih);
    split_x<<<(unsigned)(((size_t)B_ * T_ * D_ / 2 + 255) / 256), 256>>>(x);

    dim3 gig(IGNT, T_ / TG);
    ig_gemm<<<gig, 256, I_SMEM>>>(b);

    gru_persist<<<NB, 256, R_SMEM>>>(bn);

    out_kernel<<<B_, 256>>>(w_out, b_out, out);
}